// round 1
// baseline (speedup 1.0000x reference)
#include <cuda_runtime.h>
#include <cuda_bf16.h>
#include <math.h>

// DecodeSBP: per-keypoint argmax over sigmoid heatmaps.
// x: [1, 133, 512, 512] fp32.  out: [133, 3] fp32 = (x*scale, y*scale, conf) or (-4,-4,-1).
// sigmoid is strictly monotonic -> argmax(sigmoid(x)) == argmax(x); apply sigmoid
// only to the per-keypoint max.

#define KPTS 133
#define HW   (512 * 512)        // 262144 elements per keypoint
#define HW4  (HW / 4)           // 65536 float4 per keypoint
#define NTHREADS 1024
#define W 512
#define SCALE 4.0f              // INPUT_SIZE(2048) / W(512)
#define CONF_THRESHOLD 0.8f

__global__ __launch_bounds__(NTHREADS, 1)
void decode_sbp_kernel(const float* __restrict__ x, float* __restrict__ out) {
    const int k = blockIdx.x;
    const float4* __restrict__ p =
        reinterpret_cast<const float4*>(x + (size_t)k * HW);

    const int tid = threadIdx.x;

    float best = -INFINITY;
    int bidx = 0;

    // Grid-stride over 65536 float4 per keypoint: 64 iterations per thread.
    // Strictly increasing indices within a thread, so strict '>' preserves
    // first-occurrence tie-break.
    #pragma unroll 8
    for (int i = tid; i < HW4; i += NTHREADS) {
        float4 v = p[i];
        const int base = i << 2;
        if (v.x > best) { best = v.x; bidx = base;     }
        if (v.y > best) { best = v.y; bidx = base + 1; }
        if (v.z > best) { best = v.z; bidx = base + 2; }
        if (v.w > best) { best = v.w; bidx = base + 3; }
    }

    // Warp reduction: max value, ties broken by smaller index (first occurrence).
    #pragma unroll
    for (int off = 16; off > 0; off >>= 1) {
        float v2 = __shfl_down_sync(0xFFFFFFFFu, best, off);
        int   i2 = __shfl_down_sync(0xFFFFFFFFu, bidx, off);
        if (v2 > best || (v2 == best && i2 < bidx)) { best = v2; bidx = i2; }
    }

    __shared__ float s_val[32];
    __shared__ int   s_idx[32];

    const int lane = tid & 31;
    const int wid  = tid >> 5;
    if (lane == 0) { s_val[wid] = best; s_idx[wid] = bidx; }
    __syncthreads();

    // Final reduce over 32 warp results in warp 0.
    if (wid == 0) {
        best = s_val[lane];
        bidx = s_idx[lane];
        #pragma unroll
        for (int off = 16; off > 0; off >>= 1) {
            float v2 = __shfl_down_sync(0xFFFFFFFFu, best, off);
            int   i2 = __shfl_down_sync(0xFFFFFFFFu, bidx, off);
            if (v2 > best || (v2 == best && i2 < bidx)) { best = v2; bidx = i2; }
        }
        if (lane == 0) {
            const float conf = 1.0f / (1.0f + __expf(-best));
            const bool valid = conf > CONF_THRESHOLD;
            const float yy = (float)(bidx / W);
            const float xx = (float)(bidx % W);
            // Reference: invalid rows are (-1,-1,-1), then x,y columns scaled
            // for ALL rows -> invalid rows become (-4,-4,-1).
            out[k * 3 + 0] = valid ? xx * SCALE : -SCALE;
            out[k * 3 + 1] = valid ? yy * SCALE : -SCALE;
            out[k * 3 + 2] = valid ? conf : -1.0f;
        }
    }
}

extern "C" void kernel_launch(void* const* d_in, const int* in_sizes, int n_in,
                              void* d_out, int out_size) {
    const float* x = (const float*)d_in[0];
    float* out = (float*)d_out;
    decode_sbp_kernel<<<KPTS, NTHREADS>>>(x, out);
}